// round 3
// baseline (speedup 1.0000x reference)
#include <cuda_runtime.h>
#include <cuda_bf16.h>
#include <math.h>

// Problem constants
#define BB 2
#define SS 1024
#define HID 768
#define HH 12
#define DD 64
#define NORM_INV 0.125f   // 1/sqrt(64)

// ---------------- scratch (q pre-scaled, layout [B,H,S,D]) ----------------
__device__ float g_q[BB * HH * SS * DD];
__device__ float g_k[BB * HH * SS * DD];
__device__ float g_v[BB * HH * SS * DD];

// ---------------- Projection GEMM: out[b,h,s,d] = (hs @ W + b) * scale ----
// A: [2048, 768] row-major, W: [768, 768] row-major (k rows, n cols)
// Tile: BM=64, BN=64 (== D so one head per n-tile), BK=16, 256 thr, 4x4 micro
// which: 0 -> g_q (scaled by 1/8), 1 -> g_k, 2 -> g_v
__global__ __launch_bounds__(256) void qkv_gemm(
    const float* __restrict__ A, const float* __restrict__ W,
    const float* __restrict__ bias, int which)
{
    __shared__ float As[16][65];  // [k][m] transposed
    __shared__ float Bs[16][65];  // [k][n]

    const int t  = threadIdx.x;
    const int tx = t & 15;
    const int ty = t >> 4;
    const int m0 = blockIdx.y * 64;
    const int n0 = blockIdx.x * 64;

    float acc[4][4] = {};

    for (int k0 = 0; k0 < HID; k0 += 16) {
        // A tile 64x16 -> As[k][m]
        #pragma unroll
        for (int i = 0; i < 4; i++) {
            int r = ty + i * 16;        // 0..63
            As[tx][r] = A[(size_t)(m0 + r) * HID + k0 + tx];
        }
        // W tile 16x64 -> Bs[k][n]
        #pragma unroll
        for (int i = 0; i < 4; i++) {
            int r = (t >> 6) + i * 4;   // 0..15
            int c = t & 63;
            Bs[r][c] = W[(size_t)(k0 + r) * HID + n0 + c];
        }
        __syncthreads();

        #pragma unroll
        for (int kk = 0; kk < 16; kk++) {
            float a[4], b[4];
            #pragma unroll
            for (int i = 0; i < 4; i++) a[i] = As[kk][ty * 4 + i];
            #pragma unroll
            for (int j = 0; j < 4; j++) b[j] = Bs[kk][tx * 4 + j];
            #pragma unroll
            for (int i = 0; i < 4; i++)
                #pragma unroll
                for (int j = 0; j < 4; j++)
                    acc[i][j] += a[i] * b[j];
        }
        __syncthreads();
    }

    float* out  = (which == 0) ? g_q : (which == 1) ? g_k : g_v;
    const float scale = (which == 0) ? NORM_INV : 1.0f;

    // epilogue -> [B,H,S,D] (n-tile == head h)
    const int h = n0 >> 6;
    #pragma unroll
    for (int i = 0; i < 4; i++) {
        int m = m0 + ty * 4 + i;
        int b_ = m >> 10;
        int s  = m & 1023;
        float* orow = out + ((size_t)(b_ * HH + h) * SS + s) * DD;
        float4 v;
        v.x = (acc[i][0] + bias[n0 + tx * 4 + 0]) * scale;
        v.y = (acc[i][1] + bias[n0 + tx * 4 + 1]) * scale;
        v.z = (acc[i][2] + bias[n0 + tx * 4 + 2]) * scale;
        v.w = (acc[i][3] + bias[n0 + tx * 4 + 3]) * scale;
        *(float4*)(orow + tx * 4) = v;
    }
}

// ---------------- Flash attention, Br=Bc=64, fp32 --------------------------
// grid: (S/64, B*H), 256 threads. Dynamic smem (49.4 KB):
//   Qs[64*64] ([d][r]), KPs[64*65] (K as [d][c], then reused as P [r][c]),
//   Vs[64*64] ([c][d])
#define QS(d, r) Qs[(d) * 64 + (r)]
#define KS(d, c) KPs[(d) * 65 + (c)]
#define VS(c, d) Vs[(c) * 64 + (d)]
#define PS(r, c) KPs[(r) * 65 + (c)]

__global__ __launch_bounds__(256) void attn_kernel(
    const float* __restrict__ rel1, const float* __restrict__ rel2,
    const float* __restrict__ amask, const float* __restrict__ hmask,
    float* __restrict__ out)
{
    extern __shared__ float smem[];
    float* Qs  = smem;                 // 4096
    float* KPs = Qs + 64 * 64;         // 4160 (K tile, later P tile)
    float* Vs  = KPs + 64 * 65;        // 4096

    const int t  = threadIdx.x;
    const int tx = t & 15;
    const int ty = t >> 4;
    const int bh = blockIdx.y;
    const int b  = bh / HH;
    const int h  = bh % HH;
    const int s0 = blockIdx.x * 64;

    const float* qb = g_q + ((size_t)bh * SS + s0) * DD;
    const float* kb = g_k + (size_t)bh * SS * DD;
    const float* vb = g_v + (size_t)bh * SS * DD;
    const size_t biasBase = ((size_t)bh * SS + s0) * SS;
    const float* am = amask + (size_t)b * SS;

    // load Q tile transposed: Qs[d][r]
    #pragma unroll
    for (int i = 0; i < 4; i++) {
        int r = ty + i * 16;
        float4 qv = *(const float4*)(qb + (size_t)r * DD + tx * 4);
        QS(tx * 4 + 0, r) = qv.x;
        QS(tx * 4 + 1, r) = qv.y;
        QS(tx * 4 + 2, r) = qv.z;
        QS(tx * 4 + 3, r) = qv.w;
    }

    float mrow[4], lrow[4], O[4][4];
    #pragma unroll
    for (int i = 0; i < 4; i++) {
        mrow[i] = -1e30f;
        lrow[i] = 0.f;
        #pragma unroll
        for (int j = 0; j < 4; j++) O[i][j] = 0.f;
    }

    for (int t0 = 0; t0 < SS; t0 += 64) {
        // load K (transposed -> KS[d][c]) and V (natural -> VS[c][d])
        #pragma unroll
        for (int i = 0; i < 4; i++) {
            int r = ty + i * 16;  // token within tile
            float4 kv = *(const float4*)(kb + (size_t)(t0 + r) * DD + tx * 4);
            KS(tx * 4 + 0, r) = kv.x;
            KS(tx * 4 + 1, r) = kv.y;
            KS(tx * 4 + 2, r) = kv.z;
            KS(tx * 4 + 3, r) = kv.w;
            float4 vv = *(const float4*)(vb + (size_t)(t0 + r) * DD + tx * 4);
            VS(r, tx * 4 + 0) = vv.x;
            VS(r, tx * 4 + 1) = vv.y;
            VS(r, tx * 4 + 2) = vv.z;
            VS(r, tx * 4 + 3) = vv.w;
        }
        __syncthreads();

        // S tile = Q @ K^T  (q already scaled by 1/8)
        float sv[4][4] = {};
        #pragma unroll 8
        for (int d = 0; d < DD; d++) {
            float a[4], bfr[4];
            #pragma unroll
            for (int i = 0; i < 4; i++) a[i] = QS(d, ty * 4 + i);
            #pragma unroll
            for (int j = 0; j < 4; j++) bfr[j] = KS(d, tx * 4 + j);
            #pragma unroll
            for (int i = 0; i < 4; i++)
                #pragma unroll
                for (int j = 0; j < 4; j++)
                    sv[i][j] += a[i] * bfr[j];
        }

        // bias + mask
        float4 msk = *(const float4*)(am + t0 + tx * 4);
        float mk[4] = {msk.x, msk.y, msk.z, msk.w};
        #pragma unroll
        for (int i = 0; i < 4; i++) {
            int r = ty * 4 + i;
            const float* p1 = rel1 + biasBase + (size_t)r * SS + t0 + tx * 4;
            const float* p2 = rel2 + biasBase + (size_t)r * SS + t0 + tx * 4;
            float4 b1 = *(const float4*)p1;
            float4 b2 = *(const float4*)p2;
            sv[i][0] += (b1.x + b2.x) * NORM_INV + mk[0];
            sv[i][1] += (b1.y + b2.y) * NORM_INV + mk[1];
            sv[i][2] += (b1.z + b2.z) * NORM_INV + mk[2];
            sv[i][3] += (b1.w + b2.w) * NORM_INV + mk[3];
        }

        // K tile fully consumed by ALL threads before P overwrites it
        __syncthreads();

        // online softmax update (exact softmax; cogview trick is a no-op shift)
        #pragma unroll
        for (int i = 0; i < 4; i++) {
            float tmax = fmaxf(fmaxf(sv[i][0], sv[i][1]), fmaxf(sv[i][2], sv[i][3]));
            #pragma unroll
            for (int off = 8; off >= 1; off >>= 1)
                tmax = fmaxf(tmax, __shfl_xor_sync(0xffffffffu, tmax, off));
            float mnew = fmaxf(mrow[i], tmax);
            float corr = __expf(mrow[i] - mnew);
            float rs = 0.f;
            #pragma unroll
            for (int j = 0; j < 4; j++) {
                float p = __expf(sv[i][j] - mnew);
                PS(ty * 4 + i, tx * 4 + j) = p;
                rs += p;
            }
            #pragma unroll
            for (int off = 8; off >= 1; off >>= 1)
                rs += __shfl_xor_sync(0xffffffffu, rs, off);
            lrow[i] = lrow[i] * corr + rs;
            mrow[i] = mnew;
            #pragma unroll
            for (int j = 0; j < 4; j++) O[i][j] *= corr;
        }
        __syncthreads();

        // O += P @ V
        #pragma unroll 8
        for (int c = 0; c < 64; c++) {
            float a[4], bfr[4];
            #pragma unroll
            for (int i = 0; i < 4; i++) a[i] = PS(ty * 4 + i, c);
            #pragma unroll
            for (int j = 0; j < 4; j++) bfr[j] = VS(c, tx * 4 + j);
            #pragma unroll
            for (int i = 0; i < 4; i++)
                #pragma unroll
                for (int j = 0; j < 4; j++)
                    O[i][j] += a[i] * bfr[j];
        }
        __syncthreads();
    }

    // epilogue: normalize, apply head_mask, write [B,S,HID]
    const float hm = hmask[h];
    #pragma unroll
    for (int i = 0; i < 4; i++) {
        int s = s0 + ty * 4 + i;
        float inv = hm / lrow[i];
        float4 ov;
        ov.x = O[i][0] * inv;
        ov.y = O[i][1] * inv;
        ov.z = O[i][2] * inv;
        ov.w = O[i][3] * inv;
        *(float4*)(out + ((size_t)b * SS + s) * HID + h * DD + tx * 4) = ov;
    }
}

// ---------------- launch ----------------------------------------------------
extern "C" void kernel_launch(void* const* d_in, const int* in_sizes, int n_in,
                              void* d_out, int out_size)
{
    const float* hs    = (const float*)d_in[0];
    const float* amask = (const float*)d_in[1];
    const float* hmask = (const float*)d_in[2];
    const float* rel1  = (const float*)d_in[3];
    const float* rel2  = (const float*)d_in[4];
    const float* Wq    = (const float*)d_in[5];
    const float* bq    = (const float*)d_in[6];
    const float* Wk    = (const float*)d_in[7];
    const float* bk    = (const float*)d_in[8];
    const float* Wv    = (const float*)d_in[9];
    const float* bv    = (const float*)d_in[10];
    float* out = (float*)d_out;

    const int smem_attn = (64 * 64 + 64 * 65 + 64 * 64) * (int)sizeof(float);
    cudaFuncSetAttribute(attn_kernel, cudaFuncAttributeMaxDynamicSharedMemorySize, smem_attn);

    dim3 gg(HID / 64, (BB * SS) / 64);   // (12, 32)
    qkv_gemm<<<gg, 256>>>(hs, Wq, bq, 0);
    qkv_gemm<<<gg, 256>>>(hs, Wk, bk, 1);
    qkv_gemm<<<gg, 256>>>(hs, Wv, bv, 2);

    dim3 ga(SS / 64, BB * HH);           // (16, 24)
    attn_kernel<<<ga, 256, smem_attn>>>(rel1, rel2, amask, hmask, out);
}

// round 5
// speedup vs baseline: 6.5481x; 6.5481x over previous
#include <cuda_runtime.h>
#include <cuda_fp16.h>
#include <math.h>
#include <stdint.h>

#define BB 2
#define SS 1024
#define HID 768
#define HH 12
#define DD 64
#define NORM_INV 0.125f   // 1/sqrt(64)

// scratch: Q,K half [B,H,S,D] (Q pre-scaled); V half [B,H,D,S] (transposed)
__device__ __half g_q[BB*HH*SS*DD];
__device__ __half g_k[BB*HH*SS*DD];
__device__ __half g_v[BB*HH*SS*DD];

// ---------------- mma / ldmatrix helpers -----------------------------------
__device__ __forceinline__ void mma_f16(float* c, uint32_t a0, uint32_t a1,
                                        uint32_t a2, uint32_t a3,
                                        uint32_t b0, uint32_t b1) {
    asm volatile(
        "mma.sync.aligned.m16n8k16.row.col.f32.f16.f16.f32 "
        "{%0,%1,%2,%3},{%4,%5,%6,%7},{%8,%9},{%0,%1,%2,%3};\n"
        : "+f"(c[0]), "+f"(c[1]), "+f"(c[2]), "+f"(c[3])
        : "r"(a0), "r"(a1), "r"(a2), "r"(a3), "r"(b0), "r"(b1));
}
__device__ __forceinline__ void ldsm4(uint32_t* r, uint32_t a) {
    asm volatile("ldmatrix.sync.aligned.m8n8.x4.shared.b16 {%0,%1,%2,%3},[%4];\n"
                 : "=r"(r[0]), "=r"(r[1]), "=r"(r[2]), "=r"(r[3]) : "r"(a));
}
__device__ __forceinline__ void ldsm4t(uint32_t* r, uint32_t a) {
    asm volatile("ldmatrix.sync.aligned.m8n8.x4.trans.shared.b16 {%0,%1,%2,%3},[%4];\n"
                 : "=r"(r[0]), "=r"(r[1]), "=r"(r[2]), "=r"(r[3]) : "r"(a));
}
__device__ __forceinline__ uint32_t packh2(float x, float y) {
    __half2 h = __floats2half2_rn(x, y);
    return *(uint32_t*)&h;
}
__device__ __forceinline__ uint32_t smaddr(const void* p) {
    return (uint32_t)__cvta_generic_to_shared(p);
}

// ---------------- fused QKV projection (fp16 tensor cores) -----------------
// A[2048,768] fp32 @ W[768,768] fp32 (+bias, scale) -> half outputs.
// BM=128, BN=128, BK=64; 256 thr = 8 warps; warp tile 16x128 (16 n-frags).
// blockIdx.z selects (Wq->g_q scaled, Wk->g_k, Wv->g_v transposed).
__global__ __launch_bounds__(256) void qkv_proj(
    const float* __restrict__ A,
    const float* __restrict__ Wq, const float* __restrict__ Wk,
    const float* __restrict__ Wv,
    const float* __restrict__ bq, const float* __restrict__ bk,
    const float* __restrict__ bv)
{
    __shared__ __half As[128][72];   // [m][k], pad 8 -> ldmatrix conflict-free
    __shared__ __half Ws[64][136];   // [k][n], pad 8

    const int which = blockIdx.z;
    const float* W    = (which == 0) ? Wq : (which == 1) ? Wk : Wv;
    const float* bias = (which == 0) ? bq : (which == 1) ? bk : bv;

    const int t = threadIdx.x, lane = t & 31, w = t >> 5;
    const int m0 = blockIdx.y * 128, n0 = blockIdx.x * 128;

    float acc[16][4];
    #pragma unroll
    for (int i = 0; i < 16; i++)
        acc[i][0] = acc[i][1] = acc[i][2] = acc[i][3] = 0.f;

    // ldmatrix lane base addresses
    const uint32_t a_base = smaddr(&As[w * 16 + (lane & 15)][(lane >> 4) * 8]);
    const uint32_t b_base = smaddr(&Ws[(lane & 7) + ((lane >> 3) & 1) * 8][(lane >> 4) * 8]);

    for (int k0 = 0; k0 < HID; k0 += 64) {
        __syncthreads();
        // A tile 128x64 fp32 -> half
        {
            int row = t >> 1, seg = t & 1;
            const float4* src = (const float4*)(A + (size_t)(m0 + row) * HID + k0 + seg * 32);
            __half2* dst = (__half2*)&As[row][seg * 32];
            #pragma unroll
            for (int i = 0; i < 8; i++) {
                float4 v = src[i];
                dst[i * 2 + 0] = __floats2half2_rn(v.x, v.y);
                dst[i * 2 + 1] = __floats2half2_rn(v.z, v.w);
            }
        }
        // W tile 64x128 fp32 -> half (2048 float4, 8 per thread)
        {
            #pragma unroll
            for (int i = 0; i < 8; i++) {
                int gi = t + i * 256;
                int row = gi >> 5, c4 = gi & 31;
                float4 v = *(const float4*)(W + (size_t)(k0 + row) * HID + n0 + c4 * 4);
                __half2* dst = (__half2*)&Ws[row][c4 * 4];
                dst[0] = __floats2half2_rn(v.x, v.y);
                dst[1] = __floats2half2_rn(v.z, v.w);
            }
        }
        __syncthreads();

        #pragma unroll
        for (int kk = 0; kk < 64; kk += 16) {
            uint32_t af[4];
            ldsm4(af, a_base + kk * 2);
            #pragma unroll
            for (int p = 0; p < 8; p++) {
                uint32_t bf[4];
                ldsm4t(bf, b_base + kk * 272 + p * 32);
                mma_f16(acc[2 * p],     af[0], af[1], af[2], af[3], bf[0], bf[1]);
                mma_f16(acc[2 * p + 1], af[0], af[1], af[2], af[3], bf[2], bf[3]);
            }
        }
    }

    // epilogue
    const float scale = (which == 0) ? NORM_INV : 1.f;
    const int r0 = m0 + w * 16 + (lane >> 2);
    const int q2 = (lane & 3) * 2;
    #pragma unroll
    for (int nf = 0; nf < 16; nf++) {
        int n = n0 + nf * 8 + q2;
        int h = n >> 6, d = n & 63;
        float bx = bias[n], by = bias[n + 1];
        #pragma unroll
        for (int hf = 0; hf < 2; hf++) {
            int m = r0 + hf * 8;
            int b_ = m >> 10, s = m & 1023;
            float vx = (acc[nf][hf * 2 + 0] + bx) * scale;
            float vy = (acc[nf][hf * 2 + 1] + by) * scale;
            __half2 hv = __floats2half2_rn(vx, vy);
            size_t bh = (size_t)b_ * HH + h;
            if (which == 2) {   // V transposed: [bh][d][s]
                g_v[(bh * DD + d) * SS + s]     = __low2half(hv);
                g_v[(bh * DD + d + 1) * SS + s] = __high2half(hv);
            } else {
                __half* dst = ((which == 0) ? g_q : g_k) + (bh * SS + s) * DD + d;
                *(__half2*)dst = hv;
            }
        }
    }
}

// ---------------- flash attention (fp16 tensor cores) ----------------------
// Br=Bc=64; 128 threads = 4 warps x 16 rows; P stays in registers.
__global__ __launch_bounds__(128) void attn_kernel(
    const float* __restrict__ rel1, const float* __restrict__ rel2,
    const float* __restrict__ amask, const float* __restrict__ hmask,
    float* __restrict__ out)
{
    __shared__ __half Qs[64][72];   // [r][d]
    __shared__ __half Ks[64][72];   // [token][d]
    __shared__ __half Vs[64][72];   // [d][token]

    const int t = threadIdx.x, lane = t & 31, w = t >> 5;
    const int bh = blockIdx.y, b = bh / HH, h = bh % HH;
    const int s0 = blockIdx.x * 64;

    // load Q tile once
    {
        int row = t >> 1, seg = t & 1;
        const uint4* src = (const uint4*)(g_q + ((size_t)bh * SS + s0 + row) * DD + seg * 32);
        uint4* dst = (uint4*)&Qs[row][seg * 32];
        #pragma unroll
        for (int i = 0; i < 4; i++) dst[i] = src[i];
    }

    const uint32_t a_base = smaddr(&Qs[w * 16 + (lane & 15)][(lane >> 4) * 8]);
    const uint32_t kb = smaddr(&Ks[(lane & 7) + (lane >> 4) * 8][((lane >> 3) & 1) * 8]);
    const uint32_t vb = smaddr(&Vs[(lane & 7) + (lane >> 4) * 8][((lane >> 3) & 1) * 8]);

    float oacc[8][4];
    #pragma unroll
    for (int i = 0; i < 8; i++)
        oacc[i][0] = oacc[i][1] = oacc[i][2] = oacc[i][3] = 0.f;
    float m0r = -1e30f, m1r = -1e30f, l0 = 0.f, l1 = 0.f;

    const int r0g = s0 + w * 16 + (lane >> 2);
    const int q2 = (lane & 3) * 2;
    const size_t rowb0 = ((size_t)bh * SS + r0g) * SS + q2;
    const size_t rowb1 = rowb0 + (size_t)8 * SS;
    const float* amrow = amask + (size_t)b * SS + q2;

    for (int t0 = 0; t0 < SS; t0 += 64) {
        __syncthreads();   // previous iteration's smem reads complete
        // load K tile [token][d] and V tile [d][token] (both half, coalesced)
        {
            int row = t >> 1, seg = t & 1;
            const uint4* ksrc = (const uint4*)(g_k + ((size_t)bh * SS + t0 + row) * DD + seg * 32);
            uint4* kdst = (uint4*)&Ks[row][seg * 32];
            const uint4* vsrc = (const uint4*)(g_v + ((size_t)bh * DD + row) * SS + t0 + seg * 32);
            uint4* vdst = (uint4*)&Vs[row][seg * 32];
            #pragma unroll
            for (int i = 0; i < 4; i++) { kdst[i] = ksrc[i]; vdst[i] = vsrc[i]; }
        }
        // prefetch bias stream (independent of smem) — overlaps QK mma
        float2 p1a[8], p1b[8], p2a[8], p2b[8];
        #pragma unroll
        for (int nf = 0; nf < 8; nf++) {
            p1a[nf] = *(const float2*)(rel1 + rowb0 + t0 + nf * 8);
            p1b[nf] = *(const float2*)(rel1 + rowb1 + t0 + nf * 8);
            p2a[nf] = *(const float2*)(rel2 + rowb0 + t0 + nf * 8);
            p2b[nf] = *(const float2*)(rel2 + rowb1 + t0 + nf * 8);
        }
        __syncthreads();

        // S = Q @ K^T
        float sacc[8][4];
        #pragma unroll
        for (int i = 0; i < 8; i++)
            sacc[i][0] = sacc[i][1] = sacc[i][2] = sacc[i][3] = 0.f;
        #pragma unroll
        for (int kk = 0; kk < 64; kk += 16) {
            uint32_t af[4];
            ldsm4(af, a_base + kk * 2);
            #pragma unroll
            for (int p = 0; p < 4; p++) {
                uint32_t bf[4];
                ldsm4(bf, kb + p * 2304 + kk * 2);   // 16 rows * 144B
                mma_f16(sacc[2 * p],     af[0], af[1], af[2], af[3], bf[0], bf[1]);
                mma_f16(sacc[2 * p + 1], af[0], af[1], af[2], af[3], bf[2], bf[3]);
            }
        }

        // add (rel1+rel2)/8 + attention_mask
        #pragma unroll
        for (int nf = 0; nf < 8; nf++) {
            float2 am = *(const float2*)(amrow + t0 + nf * 8);
            sacc[nf][0] += (p1a[nf].x + p2a[nf].x) * NORM_INV + am.x;
            sacc[nf][1] += (p1a[nf].y + p2a[nf].y) * NORM_INV + am.y;
            sacc[nf][2] += (p1b[nf].x + p2b[nf].x) * NORM_INV + am.x;
            sacc[nf][3] += (p1b[nf].y + p2b[nf].y) * NORM_INV + am.y;
        }

        // online softmax (exact: cogview softmax == standard softmax)
        float mx0 = -1e30f, mx1 = -1e30f;
        #pragma unroll
        for (int nf = 0; nf < 8; nf++) {
            mx0 = fmaxf(mx0, fmaxf(sacc[nf][0], sacc[nf][1]));
            mx1 = fmaxf(mx1, fmaxf(sacc[nf][2], sacc[nf][3]));
        }
        mx0 = fmaxf(mx0, __shfl_xor_sync(0xffffffffu, mx0, 1));
        mx0 = fmaxf(mx0, __shfl_xor_sync(0xffffffffu, mx0, 2));
        mx1 = fmaxf(mx1, __shfl_xor_sync(0xffffffffu, mx1, 1));
        mx1 = fmaxf(mx1, __shfl_xor_sync(0xffffffffu, mx1, 2));
        float mn0 = fmaxf(m0r, mx0), mn1 = fmaxf(m1r, mx1);
        float c0 = __expf(m0r - mn0), c1 = __expf(m1r - mn1);
        float sum0 = 0.f, sum1 = 0.f;
        #pragma unroll
        for (int nf = 0; nf < 8; nf++) {
            sacc[nf][0] = __expf(sacc[nf][0] - mn0);
            sacc[nf][1] = __expf(sacc[nf][1] - mn0);
            sacc[nf][2] = __expf(sacc[nf][2] - mn1);
            sacc[nf][3] = __expf(sacc[nf][3] - mn1);
            sum0 += sacc[nf][0] + sacc[nf][1];
            sum1 += sacc[nf][2] + sacc[nf][3];
        }
        sum0 += __shfl_xor_sync(0xffffffffu, sum0, 1);
        sum0 += __shfl_xor_sync(0xffffffffu, sum0, 2);
        sum1 += __shfl_xor_sync(0xffffffffu, sum1, 1);
        sum1 += __shfl_xor_sync(0xffffffffu, sum1, 2);
        l0 = l0 * c0 + sum0;  l1 = l1 * c1 + sum1;
        m0r = mn0;  m1r = mn1;
        #pragma unroll
        for (int nf = 0; nf < 8; nf++) {
            oacc[nf][0] *= c0; oacc[nf][1] *= c0;
            oacc[nf][2] *= c1; oacc[nf][3] *= c1;
        }

        // O += P @ V  (P register C-layout == A-frag layout for m16n8k16)
        #pragma unroll
        for (int j = 0; j < 4; j++) {
            uint32_t pa0 = packh2(sacc[2 * j][0],     sacc[2 * j][1]);
            uint32_t pa1 = packh2(sacc[2 * j][2],     sacc[2 * j][3]);
            uint32_t pa2 = packh2(sacc[2 * j + 1][0], sacc[2 * j + 1][1]);
            uint32_t pa3 = packh2(sacc[2 * j + 1][2], sacc[2 * j + 1][3]);
            #pragma unroll
            for (int p = 0; p < 4; p++) {
                uint32_t bf[4];
                ldsm4(bf, vb + p * 2304 + j * 32);
                mma_f16(oacc[2 * p],     pa0, pa1, pa2, pa3, bf[0], bf[1]);
                mma_f16(oacc[2 * p + 1], pa0, pa1, pa2, pa3, bf[2], bf[3]);
            }
        }
    }

    // epilogue: normalize, head_mask, write [B,S,HID] fp32
    const float hm = hmask[h];
    const float i0 = hm / l0, i1 = hm / l1;
    const int sA = s0 + w * 16 + (lane >> 2);
    float* o0 = out + ((size_t)b * SS + sA) * HID + h * DD + q2;
    float* o1 = out + ((size_t)b * SS + sA + 8) * HID + h * DD + q2;
    #pragma unroll
    for (int nf = 0; nf < 8; nf++) {
        float2 v0 = make_float2(oacc[nf][0] * i0, oacc[nf][1] * i0);
        float2 v1 = make_float2(oacc[nf][2] * i1, oacc[nf][3] * i1);
        *(float2*)(o0 + nf * 8) = v0;
        *(float2*)(o1 + nf * 8) = v1;
    }
}

// ---------------- launch ----------------------------------------------------
extern "C" void kernel_launch(void* const* d_in, const int* in_sizes, int n_in,
                              void* d_out, int out_size)
{
    const float* hs    = (const float*)d_in[0];
    const float* amask = (const float*)d_in[1];
    const float* hmask = (const float*)d_in[2];
    const float* rel1  = (const float*)d_in[3];
    const float* rel2  = (const float*)d_in[4];
    const float* Wq    = (const float*)d_in[5];
    const float* bq    = (const float*)d_in[6];
    const float* Wk    = (const float*)d_in[7];
    const float* bk    = (const float*)d_in[8];
    const float* Wv    = (const float*)d_in[9];
    const float* bv    = (const float*)d_in[10];
    float* out = (float*)d_out;

    dim3 gp(HID / 128, (BB * SS) / 128, 3);   // (6,16,3)
    qkv_proj<<<gp, 256>>>(hs, Wq, Wk, Wv, bq, bk, bv);

    dim3 ga(SS / 64, BB * HH);                // (16,24)
    attn_kernel<<<ga, 128>>>(rel1, rel2, amask, hmask, out);
}